// round 14
// baseline (speedup 1.0000x reference)
#include <cuda_runtime.h>
#include <math.h>

// Problem constants (from reference setup_inputs)
#define B 8
#define C 64
#define SPATIAL (48*48*48)        // 110592 floats per (b,c) channel
#define SPATIAL4 (SPATIAL/4)      // 27648 float4 per channel
#define SEG4 (SPATIAL4/4)         // 6912 float4 per quarter-row
#define NBLK 2048                 // 8 batches * 256 blocks
#define BPB 256                   // blocks per batch
#define CHUNK4 (SPATIAL4/32)      // 864 float4 per copy chunk
#define R 8
#define NEG_SLOPE 0.01f

// Scratch (no cudaMalloc allowed)
__device__ float g_partials[NBLK];       // [b][c][seg]
__device__ int   g_idx[B * R];
__device__ int   g_cnt[B];               // per-batch arrival counters
__device__ int   g_flag[B];              // per-batch idx-ready flags
__device__ int   g_done = 0;             // global completion (for reset)

// ---------------------------------------------------------------------------
// One kernel, per-batch pipeline: partial sums -> per-batch barrier ->
// leader computes MLP+topk once -> all 256 batch blocks copy. Batch b's
// gather overlaps batches b+1..7's mean streaming.
// ---------------------------------------------------------------------------
__global__ __launch_bounds__(256) void se_pipeline_kernel(
    const float* __restrict__ x,
    const float* __restrict__ w1, const float* __restrict__ b1,
    const float* __restrict__ w2, const float* __restrict__ b2,
    float* __restrict__ out) {

    const int blk  = blockIdx.x;          // (b<<8) | (c<<2) | seg
    const int b    = blk >> 8;
    const int j    = blk & 255;           // within-batch block id
    const int c    = j >> 2;
    const int seg  = j & 3;
    const int t    = threadIdx.x;
    const int lane = t & 31;
    const int wrp  = t >> 5;              // 0..7

    // ---- Phase A: quarter-row partial sum for (b, c, seg) ----------------
    {
        const float4* __restrict__ p =
            reinterpret_cast<const float4*>(x + ((size_t)b * C + c) * SPATIAL)
            + seg * SEG4;

        float ax = 0.f, ay = 0.f, az = 0.f, aw = 0.f;
        // 6912 / 256 = 27 iterations
#pragma unroll 9
        for (int i = t; i < SEG4; i += 256) {
            float4 v = p[i];
            ax += v.x; ay += v.y; az += v.z; aw += v.w;
        }
        float acc = (ax + ay) + (az + aw);

        for (int off = 16; off > 0; off >>= 1)
            acc += __shfl_down_sync(0xFFFFFFFFu, acc, off);

        __shared__ float warp_sums[8];
        if (lane == 0) warp_sums[wrp] = acc;
        __syncthreads();

        if (t == 0) {
            float s = warp_sums[0] + warp_sums[1] + warp_sums[2] + warp_sums[3]
                    + warp_sums[4] + warp_sums[5] + warp_sums[6] + warp_sums[7];
            g_partials[blk] = s;
        }
    }

    // ---- Phase B: per-batch barrier + leader MLP --------------------------
    if (t == 0) {
        __threadfence();                   // release this block's partial
        atomicAdd(&g_cnt[b], 1);
    }

    if (j == 0) {
        // leader block of batch b: wait for all 256 partials of this batch
        if (t == 0) {
            while (*(volatile int*)&g_cnt[b] < BPB) __nanosleep(64);
        }
        __syncthreads();
        __threadfence();                   // acquire partials

        __shared__ float mb[C];
        __shared__ float y1s[C];
        __shared__ float zs[C];

        if (t < C) {
            float4 ps = reinterpret_cast<const float4*>(g_partials)[b * C + t];
            mb[t] = ((ps.x + ps.y) + (ps.z + ps.w)) * (1.0f / (float)SPATIAL);
        }
        __syncthreads();

        // layer 1: warp w -> channels 8w..8w+7 (coalesced global weights)
        {
            const float m0 = mb[lane];
            const float m1 = mb[lane + 32];
#pragma unroll
            for (int cc = 0; cc < 8; cc++) {
                const int i = 8 * wrp + cc;
                const float* __restrict__ wr = w1 + i * C;
                float a = m0 * wr[lane] + m1 * wr[lane + 32];
#pragma unroll
                for (int off = 16; off > 0; off >>= 1)
                    a += __shfl_down_sync(0xFFFFFFFFu, a, off);
                if (lane == 0) {
                    a += b1[i];
                    y1s[i] = (a > 0.0f) ? a : NEG_SLOPE * a;
                }
            }
        }
        __syncthreads();

        // layer 2: same with w2, sigmoid
        {
            const float h0 = y1s[lane];
            const float h1 = y1s[lane + 32];
#pragma unroll
            for (int cc = 0; cc < 8; cc++) {
                const int i = 8 * wrp + cc;
                const float* __restrict__ wr = w2 + i * C;
                float a = h0 * wr[lane] + h1 * wr[lane + 32];
#pragma unroll
                for (int off = 16; off > 0; off >>= 1)
                    a += __shfl_down_sync(0xFFFFFFFFu, a, off);
                if (lane == 0) {
                    a += b2[i];
                    zs[i] = 1.0f / (1.0f + expf(-a));
                }
            }
        }
        __syncthreads();

        // rank-based top-8: rank(j') = #{channels beating j'} with
        // smaller-index tie-break == jax.lax.top_k order.
        if (t < C) {
            const float z = zs[t];
            int rank = 0;
#pragma unroll
            for (int jj = 0; jj < C; jj++) {
                const float v = zs[jj];
                rank += (v > z) || (v == z && jj < t);
            }
            if (rank < R) g_idx[b * R + rank] = t;
        }
        __syncthreads();

        if (t == 0) {
            __threadfence();               // release idx
            *(volatile int*)&g_flag[b] = 1;
        }
        __syncthreads();
    } else {
        // non-leader: wait for this batch's idx
        if (t == 0) {
            while (*(volatile int*)&g_flag[b] == 0) __nanosleep(64);
        }
        __syncthreads();
        __threadfence();                   // acquire idx
    }

    // ---- Phase C: copy this block's chunk ---------------------------------
    {
        const int row_r = j >> 5;          // 0..7 : output rank within batch
        const int chunk = j & 31;          // 0..31
        const int ch = g_idx[b * R + row_r];

        const float4* __restrict__ src =
            reinterpret_cast<const float4*>(x + ((size_t)b * C + ch) * SPATIAL)
            + chunk * CHUNK4;
        float4* __restrict__ dst =
            reinterpret_cast<float4*>(out) + (size_t)(b * R + row_r) * SPATIAL4
            + chunk * CHUNK4;

        // 864 = 3*256 + 96
#pragma unroll
        for (int k = 0; k < 4; k++) {
            const int i = k * 256 + t;
            if (i < CHUNK4) __stcs(dst + i, src[i]);
        }
    }

    // ---- Reset counters for next graph replay (last finisher) -------------
    if (t == 0) {
        const int d = atomicAdd(&g_done, 1);
        if (d == NBLK - 1) {
#pragma unroll
            for (int bb = 0; bb < B; bb++) { g_cnt[bb] = 0; g_flag[bb] = 0; }
            g_done = 0;
        }
    }
}

// ---------------------------------------------------------------------------
extern "C" void kernel_launch(void* const* d_in, const int* in_sizes, int n_in,
                              void* d_out, int out_size) {
    const float* x  = (const float*)d_in[0];
    const float* w1 = (const float*)d_in[1];
    const float* b1 = (const float*)d_in[2];
    const float* w2 = (const float*)d_in[3];
    const float* b2 = (const float*)d_in[4];
    float* out = (float*)d_out;

    se_pipeline_kernel<<<NBLK, 256>>>(x, w1, b1, w2, b2, out);
}

// round 15
// speedup vs baseline: 1.2617x; 1.2617x over previous
#include <cuda_runtime.h>
#include <math.h>

// Problem constants (from reference setup_inputs)
#define B 8
#define C 64
#define SPATIAL (48*48*48)        // 110592 floats per (b,c) channel
#define SPATIAL4 (SPATIAL/4)      // 27648 float4 per channel
#define SEGS 4                    // quarter-row segments
#define SEG4 (SPATIAL4/SEGS)      // 6912 float4 per segment
#define NBLK1 (B*C*SEGS)          // 2048 reduction blocks
#define R 8
#define NEG_SLOPE 0.01f

// gather kernel geometry: 9 chunks per row, 512 threads, 6 float4/thread
#define GT 512
#define GK 6
#define GBX 9                     // 9*512*6 = 27648 = SPATIAL4 exactly

// Scratch (no cudaMalloc allowed)
__device__ float g_partials[NBLK1];

// ---------------------------------------------------------------------------
// Kernel 1: quarter-row partial sums. 2048 blocks x 256 threads (measured
// 36.6us @ 79.7% DRAM — bandwidth saturated). PDL trigger at end.
// ---------------------------------------------------------------------------
__global__ __launch_bounds__(256) void mean_partial_kernel(
    const float* __restrict__ x, float* __restrict__ partials) {
    const int blk = blockIdx.x;          // row*4 + seg
    const int row = blk >> 2;
    const int seg = blk & 3;
    const float4* __restrict__ p =
        reinterpret_cast<const float4*>(x + (size_t)row * SPATIAL) + seg * SEG4;

    float ax = 0.f, ay = 0.f, az = 0.f, aw = 0.f;
    // 6912 / 256 = 27 iterations
#pragma unroll 9
    for (int i = threadIdx.x; i < SEG4; i += 256) {
        float4 v = p[i];
        ax += v.x; ay += v.y; az += v.z; aw += v.w;
    }
    float acc = (ax + ay) + (az + aw);

    for (int off = 16; off > 0; off >>= 1)
        acc += __shfl_down_sync(0xFFFFFFFFu, acc, off);

    __shared__ float warp_sums[8];
    const int lane = threadIdx.x & 31;
    const int wid  = threadIdx.x >> 5;
    if (lane == 0) warp_sums[wid] = acc;
    __syncthreads();

    if (threadIdx.x == 0) {
        float s = warp_sums[0] + warp_sums[1] + warp_sums[2] + warp_sums[3]
                + warp_sums[4] + warp_sums[5] + warp_sums[6] + warp_sums[7];
        partials[blk] = s;
        cudaTriggerProgrammaticLaunchCompletion();
    }
}

// ---------------------------------------------------------------------------
// Kernel 2 (PDL secondary): register-prefetched warp-cooperative MLP +
// register means + rank pick + copy. Warp w owns channels 4w..4w+3; weight
// slices live in registers, prefetched BEFORE the grid sync. Post-sync:
// each lane loads its two channels' partials directly (no smem stage),
// two shuffle-reduce layers, rank-based pick, copy. Deterministic:
// identical FP sequence in every block. grid = (9, 64), 512 threads.
// ---------------------------------------------------------------------------
__global__ __launch_bounds__(GT) void gather_mlp_kernel(
    const float* __restrict__ x,
    const float* __restrict__ w1, const float* __restrict__ b1,
    const float* __restrict__ w2, const float* __restrict__ b2,
    const float* __restrict__ partials,
    float* __restrict__ out) {

    __shared__ float y1s[C];
    __shared__ float zs[C];
    __shared__ int   ch_s;

    const int row = blockIdx.y;      // 0..63 : b*R + r
    const int b   = row >> 3;
    const int r   = row & 7;
    const int t   = threadIdx.x;
    const int lane = t & 31;
    const int wrp  = t >> 5;         // 0..15

    // ---- Pre-sync: prefetch this warp's weight slices into registers ------
    float w1a[4], w1b[4], w2a[4], w2b[4];
#pragma unroll
    for (int c = 0; c < 4; c++) {
        const int i = 4 * wrp + c;
        w1a[c] = w1[i * C + lane];
        w1b[c] = w1[i * C + 32 + lane];
        w2a[c] = w2[i * C + lane];
        w2b[c] = w2[i * C + 32 + lane];
    }
    const float bias1 = (lane < 4) ? b1[4 * wrp + lane] : 0.f;
    const float bias2 = (lane < 4) ? b2[4 * wrp + lane] : 0.f;

    // ---- Wait for kernel 1's partials -------------------------------------
    cudaGridDependencySynchronize();

    // Register means: lane l computes mean of channel l (m0) and l+32 (m1)
    // straight from the partials — no smem stage, no extra sync.
    const float4 p0 = reinterpret_cast<const float4*>(partials)[b * C + lane];
    const float4 p1 = reinterpret_cast<const float4*>(partials)[b * C + lane + 32];
    const float m0 = ((p0.x + p0.y) + (p0.z + p0.w)) * (1.0f / (float)SPATIAL);
    const float m1 = ((p1.x + p1.y) + (p1.z + p1.w)) * (1.0f / (float)SPATIAL);

    // layer 1: warp w -> channels 4w..4w+3 (registers + shuffle reduce)
#pragma unroll
    for (int c = 0; c < 4; c++) {
        float a = m0 * w1a[c] + m1 * w1b[c];
#pragma unroll
        for (int off = 16; off > 0; off >>= 1)
            a += __shfl_down_sync(0xFFFFFFFFu, a, off);
        const float bi = __shfl_sync(0xFFFFFFFFu, bias1, c);
        if (lane == 0) {
            a += bi;
            y1s[4 * wrp + c] = (a > 0.0f) ? a : NEG_SLOPE * a;
        }
    }
    __syncthreads();

    // layer 2: same with w2, sigmoid
    {
        const float h0 = y1s[lane];
        const float h1 = y1s[lane + 32];
#pragma unroll
        for (int c = 0; c < 4; c++) {
            float a = h0 * w2a[c] + h1 * w2b[c];
#pragma unroll
            for (int off = 16; off > 0; off >>= 1)
                a += __shfl_down_sync(0xFFFFFFFFu, a, off);
            const float bi = __shfl_sync(0xFFFFFFFFu, bias2, c);
            if (lane == 0) {
                a += bi;
                zs[4 * wrp + c] = 1.0f / (1.0f + expf(-a));
            }
        }
    }
    __syncthreads();

    // Rank-based selection: rank(j) = #{j' : z[j'] > z[j] or (== and j'<j)}.
    // Channel with rank == r is the r-th pick of repeated strict-argmax with
    // smaller-index tie-break (jax.lax.top_k order).
    if (t < C) {
        const float z = zs[t];
        int rank = 0;
#pragma unroll
        for (int jj = 0; jj < C; jj++) {
            const float v = zs[jj];
            rank += (v > z) || (v == z && jj < t);
        }
        if (rank == r) ch_s = t;
    }
    __syncthreads();

    // Copy this block's chunk of the selected channel: 6 float4 per thread.
    const int ch = ch_s;
    const float4* __restrict__ src =
        reinterpret_cast<const float4*>(x + ((size_t)b * C + ch) * SPATIAL);
    float4* __restrict__ dst =
        reinterpret_cast<float4*>(out) + (size_t)row * SPATIAL4;

#pragma unroll
    for (int k = 0; k < GK; k++) {
        const int i = (blockIdx.x * GK + k) * GT + t;  // 0..27647
        dst[i] = src[i];
    }
}

// ---------------------------------------------------------------------------
extern "C" void kernel_launch(void* const* d_in, const int* in_sizes, int n_in,
                              void* d_out, int out_size) {
    const float* x  = (const float*)d_in[0];
    const float* w1 = (const float*)d_in[1];
    const float* b1 = (const float*)d_in[2];
    const float* w2 = (const float*)d_in[3];
    const float* b2 = (const float*)d_in[4];
    float* out = (float*)d_out;

    float* partials;
    cudaGetSymbolAddress((void**)&partials, g_partials);

    mean_partial_kernel<<<NBLK1, 256>>>(x, partials);

    // PDL launch: blocks prefetch weights into registers while kernel 1
    // drains; cudaGridDependencySynchronize() gates the partials.
    cudaLaunchConfig_t cfg = {};
    cfg.gridDim  = dim3(GBX, B * R, 1);   // (9, 64)
    cfg.blockDim = dim3(GT, 1, 1);
    cudaLaunchAttribute attrs[1];
    attrs[0].id = cudaLaunchAttributeProgrammaticStreamSerialization;
    attrs[0].val.programmaticStreamSerializationAllowed = 1;
    cfg.attrs = attrs;
    cfg.numAttrs = 1;
    cudaLaunchKernelEx(&cfg, gather_mlp_kernel, x, w1, b1, w2, b2,
                       (const float*)partials, out);
}

// round 16
// speedup vs baseline: 1.2743x; 1.0100x over previous
#include <cuda_runtime.h>
#include <math.h>

// Problem constants (from reference setup_inputs)
#define B 8
#define C 64
#define SPATIAL (48*48*48)        // 110592 floats per (b,c) channel
#define SPATIAL4 (SPATIAL/4)      // 27648 float4 per channel
#define SEGS 4                    // quarter-row segments
#define SEG4 (SPATIAL4/SEGS)      // 6912 float4 per segment
#define NBLK1 (B*C*SEGS)          // 2048 reduction blocks
#define R 8
#define NEG_SLOPE 0.01f

// gather kernel geometry (R13 champion): 6 chunks/row, 512 thr, 9 float4/thr
#define GT 512
#define GK 9
#define GBX 6                     // 6*512*9 = 27648 = SPATIAL4 exactly

// Scratch (no cudaMalloc allowed)
__device__ float g_partials[NBLK1];

// ---------------------------------------------------------------------------
// Kernel 1: quarter-row partial sums. 2048 blocks x 256 threads (measured
// 36.6us @ 79.7% DRAM — bandwidth saturated). PDL trigger at end.
// ---------------------------------------------------------------------------
__global__ __launch_bounds__(256) void mean_partial_kernel(
    const float* __restrict__ x, float* __restrict__ partials) {
    const int blk = blockIdx.x;          // row*4 + seg
    const int row = blk >> 2;
    const int seg = blk & 3;
    const float4* __restrict__ p =
        reinterpret_cast<const float4*>(x + (size_t)row * SPATIAL) + seg * SEG4;

    float ax = 0.f, ay = 0.f, az = 0.f, aw = 0.f;
    // 6912 / 256 = 27 iterations
#pragma unroll 9
    for (int i = threadIdx.x; i < SEG4; i += 256) {
        float4 v = p[i];
        ax += v.x; ay += v.y; az += v.z; aw += v.w;
    }
    float acc = (ax + ay) + (az + aw);

    for (int off = 16; off > 0; off >>= 1)
        acc += __shfl_down_sync(0xFFFFFFFFu, acc, off);

    __shared__ float warp_sums[8];
    const int lane = threadIdx.x & 31;
    const int wid  = threadIdx.x >> 5;
    if (lane == 0) warp_sums[wid] = acc;
    __syncthreads();

    if (threadIdx.x == 0) {
        float s = warp_sums[0] + warp_sums[1] + warp_sums[2] + warp_sums[3]
                + warp_sums[4] + warp_sums[5] + warp_sums[6] + warp_sums[7];
        partials[blk] = s;
        cudaTriggerProgrammaticLaunchCompletion();
    }
}

// ---------------------------------------------------------------------------
// Kernel 2 (PDL secondary): R13 structure + register means.
// Warp w owns channels 4w..4w+3; weight slices prefetched into registers
// BEFORE the grid sync (overlaps kernel-1 tail). Post-sync: each lane loads
// its two channels' partials directly (no smem stage), two shuffle-reduce
// layers, rank-based pick, copy. Deterministic: identical FP sequence in
// every block. grid = (6, 64), 512 threads, 9 float4/thread.
// ---------------------------------------------------------------------------
__global__ __launch_bounds__(GT) void gather_mlp_kernel(
    const float* __restrict__ x,
    const float* __restrict__ w1, const float* __restrict__ b1,
    const float* __restrict__ w2, const float* __restrict__ b2,
    const float* __restrict__ partials,
    float* __restrict__ out) {

    __shared__ float y1s[C];
    __shared__ float zs[C];
    __shared__ int   ch_s;

    const int row = blockIdx.y;      // 0..63 : b*R + r
    const int b   = row >> 3;
    const int r   = row & 7;
    const int t   = threadIdx.x;
    const int lane = t & 31;
    const int wrp  = t >> 5;         // 0..15

    // ---- Pre-sync: prefetch this warp's weight slices into registers ------
    float w1a[4], w1b[4], w2a[4], w2b[4];
#pragma unroll
    for (int c = 0; c < 4; c++) {
        const int i = 4 * wrp + c;
        w1a[c] = w1[i * C + lane];
        w1b[c] = w1[i * C + 32 + lane];
        w2a[c] = w2[i * C + lane];
        w2b[c] = w2[i * C + 32 + lane];
    }
    const float bias1 = (lane < 4) ? b1[4 * wrp + lane] : 0.f;
    const float bias2 = (lane < 4) ? b2[4 * wrp + lane] : 0.f;

    // ---- Wait for kernel 1's partials -------------------------------------
    cudaGridDependencySynchronize();

    // Register means: lane l holds the mean of channel l (m0) and l+32 (m1),
    // loaded straight from the partials — no smem stage, no extra sync.
    const float4 p0 = reinterpret_cast<const float4*>(partials)[b * C + lane];
    const float4 p1 = reinterpret_cast<const float4*>(partials)[b * C + lane + 32];
    const float m0 = ((p0.x + p0.y) + (p0.z + p0.w)) * (1.0f / (float)SPATIAL);
    const float m1 = ((p1.x + p1.y) + (p1.z + p1.w)) * (1.0f / (float)SPATIAL);

    // layer 1: warp w -> channels 4w..4w+3 (registers + shuffle reduce)
#pragma unroll
    for (int c = 0; c < 4; c++) {
        float a = m0 * w1a[c] + m1 * w1b[c];
#pragma unroll
        for (int off = 16; off > 0; off >>= 1)
            a += __shfl_down_sync(0xFFFFFFFFu, a, off);
        const float bi = __shfl_sync(0xFFFFFFFFu, bias1, c);
        if (lane == 0) {
            a += bi;
            y1s[4 * wrp + c] = (a > 0.0f) ? a : NEG_SLOPE * a;
        }
    }
    __syncthreads();

    // layer 2: same with w2, sigmoid
    {
        const float h0 = y1s[lane];
        const float h1 = y1s[lane + 32];
#pragma unroll
        for (int c = 0; c < 4; c++) {
            float a = h0 * w2a[c] + h1 * w2b[c];
#pragma unroll
            for (int off = 16; off > 0; off >>= 1)
                a += __shfl_down_sync(0xFFFFFFFFu, a, off);
            const float bi = __shfl_sync(0xFFFFFFFFu, bias2, c);
            if (lane == 0) {
                a += bi;
                zs[4 * wrp + c] = 1.0f / (1.0f + expf(-a));
            }
        }
    }
    __syncthreads();

    // Rank-based selection: rank(j) = #{j' : z[j'] > z[j] or (== and j'<j)}.
    // Channel with rank == r is the r-th pick of repeated strict-argmax with
    // smaller-index tie-break (jax.lax.top_k order).
    if (t < C) {
        const float z = zs[t];
        int rank = 0;
#pragma unroll
        for (int jj = 0; jj < C; jj++) {
            const float v = zs[jj];
            rank += (v > z) || (v == z && jj < t);
        }
        if (rank == r) ch_s = t;
    }
    __syncthreads();

    // Copy this block's chunk of the selected channel: 9 float4 per thread.
    const int ch = ch_s;
    const float4* __restrict__ src =
        reinterpret_cast<const float4*>(x + ((size_t)b * C + ch) * SPATIAL);
    float4* __restrict__ dst =
        reinterpret_cast<float4*>(out) + (size_t)row * SPATIAL4;

#pragma unroll
    for (int k = 0; k < GK; k++) {
        const int i = (blockIdx.x * GK + k) * GT + t;  // 0..27647
        dst[i] = src[i];
    }
}

// ---------------------------------------------------------------------------
extern "C" void kernel_launch(void* const* d_in, const int* in_sizes, int n_in,
                              void* d_out, int out_size) {
    const float* x  = (const float*)d_in[0];
    const float* w1 = (const float*)d_in[1];
    const float* b1 = (const float*)d_in[2];
    const float* w2 = (const float*)d_in[3];
    const float* b2 = (const float*)d_in[4];
    float* out = (float*)d_out;

    float* partials;
    cudaGetSymbolAddress((void**)&partials, g_partials);

    mean_partial_kernel<<<NBLK1, 256>>>(x, partials);

    // PDL launch: blocks prefetch weights into registers while kernel 1
    // drains; cudaGridDependencySynchronize() gates the partials.
    cudaLaunchConfig_t cfg = {};
    cfg.gridDim  = dim3(GBX, B * R, 1);   // (6, 64)
    cfg.blockDim = dim3(GT, 1, 1);
    cudaLaunchAttribute attrs[1];
    attrs[0].id = cudaLaunchAttributeProgrammaticStreamSerialization;
    attrs[0].val.programmaticStreamSerializationAllowed = 1;
    cfg.attrs = attrs;
    cfg.numAttrs = 1;
    cudaLaunchKernelEx(&cfg, gather_mlp_kernel, x, w1, b1, w2, b2,
                       (const float*)partials, out);
}

// round 17
// speedup vs baseline: 1.2782x; 1.0031x over previous
#include <cuda_runtime.h>
#include <math.h>

// Problem constants (from reference setup_inputs)
#define B 8
#define C 64
#define SPATIAL (48*48*48)        // 110592 floats per (b,c) channel
#define SPATIAL4 (SPATIAL/4)      // 27648 float4 per channel
#define SEGS 4                    // quarter-row segments
#define SEG4 (SPATIAL4/SEGS)      // 6912 float4 per segment
#define NBLK1 (B*C*SEGS)          // 2048 reduction blocks
#define R 8
#define NEG_SLOPE 0.01f

// gather kernel geometry (champion): 6 chunks/row, 512 thr, 9 float4/thr
#define GT 512
#define GK 9
#define GBX 6                     // 6*512*9 = 27648 = SPATIAL4 exactly

// Scratch (no cudaMalloc allowed)
__device__ float g_partials[NBLK1];

// ---------------------------------------------------------------------------
// Kernel 1: quarter-row partial sums. 2048 blocks x 256 threads.
// Streaming loads (__ldcs): x is read-once here; don't pollute L2.
// PDL trigger at end.
// ---------------------------------------------------------------------------
__global__ __launch_bounds__(256) void mean_partial_kernel(
    const float* __restrict__ x, float* __restrict__ partials) {
    const int blk = blockIdx.x;          // row*4 + seg
    const int row = blk >> 2;
    const int seg = blk & 3;
    const float4* __restrict__ p =
        reinterpret_cast<const float4*>(x + (size_t)row * SPATIAL) + seg * SEG4;

    float ax = 0.f, ay = 0.f, az = 0.f, aw = 0.f;
    // 6912 / 256 = 27 iterations
#pragma unroll 9
    for (int i = threadIdx.x; i < SEG4; i += 256) {
        float4 v = __ldcs(p + i);
        ax += v.x; ay += v.y; az += v.z; aw += v.w;
    }
    float acc = (ax + ay) + (az + aw);

    for (int off = 16; off > 0; off >>= 1)
        acc += __shfl_down_sync(0xFFFFFFFFu, acc, off);

    __shared__ float warp_sums[8];
    const int lane = threadIdx.x & 31;
    const int wid  = threadIdx.x >> 5;
    if (lane == 0) warp_sums[wid] = acc;
    __syncthreads();

    if (threadIdx.x == 0) {
        float s = warp_sums[0] + warp_sums[1] + warp_sums[2] + warp_sums[3]
                + warp_sums[4] + warp_sums[5] + warp_sums[6] + warp_sums[7];
        partials[blk] = s;
        cudaTriggerProgrammaticLaunchCompletion();
    }
}

// ---------------------------------------------------------------------------
// Kernel 2 (PDL secondary): register-prefetched warp-cooperative MLP +
// register means + rank pick + streaming copy. Warp w owns channels
// 4w..4w+3; weight slices prefetched into registers BEFORE the grid sync.
// Deterministic: identical FP sequence in every block.
// grid = (6, 64), 512 threads, 9 float4/thread.
// ---------------------------------------------------------------------------
__global__ __launch_bounds__(GT) void gather_mlp_kernel(
    const float* __restrict__ x,
    const float* __restrict__ w1, const float* __restrict__ b1,
    const float* __restrict__ w2, const float* __restrict__ b2,
    const float* __restrict__ partials,
    float* __restrict__ out) {

    __shared__ float y1s[C];
    __shared__ float zs[C];
    __shared__ int   ch_s;

    const int row = blockIdx.y;      // 0..63 : b*R + r
    const int b   = row >> 3;
    const int r   = row & 7;
    const int t   = threadIdx.x;
    const int lane = t & 31;
    const int wrp  = t >> 5;         // 0..15

    // ---- Pre-sync: prefetch this warp's weight slices into registers ------
    float w1a[4], w1b[4], w2a[4], w2b[4];
#pragma unroll
    for (int c = 0; c < 4; c++) {
        const int i = 4 * wrp + c;
        w1a[c] = w1[i * C + lane];
        w1b[c] = w1[i * C + 32 + lane];
        w2a[c] = w2[i * C + lane];
        w2b[c] = w2[i * C + 32 + lane];
    }
    const float bias1 = (lane < 4) ? b1[4 * wrp + lane] : 0.f;
    const float bias2 = (lane < 4) ? b2[4 * wrp + lane] : 0.f;

    // ---- Wait for kernel 1's partials -------------------------------------
    cudaGridDependencySynchronize();

    // Register means: lane l holds the mean of channel l (m0) and l+32 (m1).
    const float4 p0 = reinterpret_cast<const float4*>(partials)[b * C + lane];
    const float4 p1 = reinterpret_cast<const float4*>(partials)[b * C + lane + 32];
    const float m0 = ((p0.x + p0.y) + (p0.z + p0.w)) * (1.0f / (float)SPATIAL);
    const float m1 = ((p1.x + p1.y) + (p1.z + p1.w)) * (1.0f / (float)SPATIAL);

    // layer 1: warp w -> channels 4w..4w+3 (registers + shuffle reduce)
#pragma unroll
    for (int c = 0; c < 4; c++) {
        float a = m0 * w1a[c] + m1 * w1b[c];
#pragma unroll
        for (int off = 16; off > 0; off >>= 1)
            a += __shfl_down_sync(0xFFFFFFFFu, a, off);
        const float bi = __shfl_sync(0xFFFFFFFFu, bias1, c);
        if (lane == 0) {
            a += bi;
            y1s[4 * wrp + c] = (a > 0.0f) ? a : NEG_SLOPE * a;
        }
    }
    __syncthreads();

    // layer 2: same with w2, sigmoid
    {
        const float h0 = y1s[lane];
        const float h1 = y1s[lane + 32];
#pragma unroll
        for (int c = 0; c < 4; c++) {
            float a = h0 * w2a[c] + h1 * w2b[c];
#pragma unroll
            for (int off = 16; off > 0; off >>= 1)
                a += __shfl_down_sync(0xFFFFFFFFu, a, off);
            const float bi = __shfl_sync(0xFFFFFFFFu, bias2, c);
            if (lane == 0) {
                a += bi;
                zs[4 * wrp + c] = 1.0f / (1.0f + expf(-a));
            }
        }
    }
    __syncthreads();

    // Rank-based selection: rank(j) = #{j' : z[j'] > z[j] or (== and j'<j)}.
    // Channel with rank == r is the r-th pick of repeated strict-argmax with
    // smaller-index tie-break (jax.lax.top_k order).
    if (t < C) {
        const float z = zs[t];
        int rank = 0;
#pragma unroll
        for (int jj = 0; jj < C; jj++) {
            const float v = zs[jj];
            rank += (v > z) || (v == z && jj < t);
        }
        if (rank == r) ch_s = t;
    }
    __syncthreads();

    // Copy this block's chunk: read-once src (__ldcs), write-once dst (__stcs).
    const int ch = ch_s;
    const float4* __restrict__ src =
        reinterpret_cast<const float4*>(x + ((size_t)b * C + ch) * SPATIAL);
    float4* __restrict__ dst =
        reinterpret_cast<float4*>(out) + (size_t)row * SPATIAL4;

#pragma unroll
    for (int k = 0; k < GK; k++) {
        const int i = (blockIdx.x * GK + k) * GT + t;  // 0..27647
        __stcs(dst + i, __ldcs(src + i));
    }
}

// ---------------------------------------------------------------------------
extern "C" void kernel_launch(void* const* d_in, const int* in_sizes, int n_in,
                              void* d_out, int out_size) {
    const float* x  = (const float*)d_in[0];
    const float* w1 = (const float*)d_in[1];
    const float* b1 = (const float*)d_in[2];
    const float* w2 = (const float*)d_in[3];
    const float* b2 = (const float*)d_in[4];
    float* out = (float*)d_out;

    float* partials;
    cudaGetSymbolAddress((void**)&partials, g_partials);

    mean_partial_kernel<<<NBLK1, 256>>>(x, partials);

    // PDL launch: blocks prefetch weights into registers while kernel 1
    // drains; cudaGridDependencySynchronize() gates the partials.
    cudaLaunchConfig_t cfg = {};
    cfg.gridDim  = dim3(GBX, B * R, 1);   // (6, 64)
    cfg.blockDim = dim3(GT, 1, 1);
    cudaLaunchAttribute attrs[1];
    attrs[0].id = cudaLaunchAttributeProgrammaticStreamSerialization;
    attrs[0].val.programmaticStreamSerializationAllowed = 1;
    cfg.attrs = attrs;
    cfg.numAttrs = 1;
    cudaLaunchKernelEx(&cfg, gather_mlp_kernel, x, w1, b1, w2, b2,
                       (const float*)partials, out);
}